// round 8
// baseline (speedup 1.0000x reference)
#include <cuda_runtime.h>

// Problem constants: B=2048, F=40, E=64, I=780
#define FDIM   40
#define EDIM   64
#define NPAIR  780
#define NGR    10            // field groups of 4
#define NFULL  45            // C(10,2) full 4x4 tiles
#define NTILE  55            // + 10 diagonal (intra-group) tiles
#define BT     8             // batches per block; lane = 4*b + q

__device__ float g_ksum[NPAIR * EDIM];

// ---------------------------------------------------------------------------
// Kernel 1: ksum[p][e] = sum_k kernel[k][p][e]
// ---------------------------------------------------------------------------
__global__ void ksum_kernel(const float* __restrict__ kern)
{
    const int n4 = NPAIR * EDIM / 4;
    int idx4 = blockIdx.x * blockDim.x + threadIdx.x;
    if (idx4 >= n4) return;
    const float4* k4 = reinterpret_cast<const float4*>(kern);
    float4 s = make_float4(0.f, 0.f, 0.f, 0.f);
    #pragma unroll 8
    for (int k = 0; k < EDIM; ++k) {
        float4 v = k4[(size_t)k * n4 + idx4];
        s.x += v.x; s.y += v.y; s.z += v.z; s.w += v.w;
    }
    reinterpret_cast<float4*>(g_ksum)[idx4] = s;
}

// ---------------------------------------------------------------------------
// f32x2 packed-math helpers
// ---------------------------------------------------------------------------
__device__ __forceinline__ unsigned long long mul2(unsigned long long a,
                                                   unsigned long long b)
{
    unsigned long long r;
    asm("mul.rn.f32x2 %0, %1, %2;" : "=l"(r) : "l"(a), "l"(b));
    return r;
}
__device__ __forceinline__ unsigned long long fma2(unsigned long long a,
                                                   unsigned long long b,
                                                   unsigned long long c)
{
    unsigned long long r;
    asm("fma.rn.f32x2 %0, %1, %2, %3;" : "=l"(r) : "l"(a), "l"(b), "l"(c));
    return r;
}
__device__ __forceinline__ float sum2(unsigned long long a)
{
    float lo, hi;
    asm("mov.b64 {%0, %1}, %2;" : "=f"(lo), "=f"(hi) : "l"(a));
    return lo + hi;
}

__device__ __forceinline__ int pair_off(int i) { return i * 39 - (i * (i - 1)) / 2; }

// ---------------------------------------------------------------------------
// Kernel 2, two e-phases of 32. Per phase, smem holds 8 batches x 40 fields
// x 8 float4 chunks (40 KB):  sm4[(f*2 + (c&1))*32 + (c>>1)*8 + b].
// Lane l = 4b+q reads (f, s) at entry q*8+b  -> permutation of 0..31,
// conflict-free LDS.128. Grid = 256 batch-groups x 2 tile-halves.
// ---------------------------------------------------------------------------
__global__ void __launch_bounds__(256, 3) interact_kernel(
    const float* __restrict__ A,    // (B, 40, 64)
    float*       __restrict__ out)  // (B, 780)
{
    extern __shared__ ulonglong2 sm4[];   // 2560 entries = 40 KB

    const int tid  = threadIdx.x;
    const int lane = tid & 31;
    const int warp = tid >> 5;
    const int bg   = blockIdx.x >> 1;
    const int half = blockIdx.x & 1;
    const int b0   = bg * BT;

    const int q  = lane & 3;       // e-quarter within phase (2 chunks each)
    const int bq = lane >> 2;      // batch within block
    float* orow = out + (size_t)(b0 + bq) * NPAIR;

    const float4* A4 = reinterpret_cast<const float4*>(A);
    const ulonglong2* w4 = reinterpret_cast<const ulonglong2*>(g_ksum);

    for (int ph = 0; ph < 2; ++ph) {
        if (ph) __syncthreads();   // finish phase-0 compute before restage

        // ---- stage 8 batches x 40 fields x 8 chunks (this phase) ----
        #pragma unroll
        for (int it = 0; it < 10; ++it) {
            int v = it * 256 + tid;
            int b = v & 7;
            int c = (v >> 3) & 7;
            int f = v >> 6;
            float4 val = A4[(size_t)(b0 + b) * (FDIM * 16) + f * 16 + ph * 8 + c];
            sm4[(f * 2 + (c & 1)) * 32 + (c >> 1) * 8 + b] =
                *reinterpret_cast<ulonglong2*>(&val);
        }
        __syncthreads();

        // ---- tiles of this half: t = half, half+2, ... ----
        for (int t = half + 2 * warp; t < NTILE; t += 16) {
            if (t < NFULL) {
                // full 4x4 tile between groups gi < gj
                int gi = 0, cum = 0;
                while (cum + (NGR - 1 - gi) <= t) { cum += NGR - 1 - gi; ++gi; }
                int gj = gi + 1 + (t - cum);
                const int i0 = 4 * gi, j0 = 4 * gj;

                int pb[4];
                #pragma unroll
                for (int a = 0; a < 4; ++a)
                    pb[a] = pair_off(i0 + a) + (j0 - (i0 + a) - 1);

                unsigned long long acc[16];
                #pragma unroll
                for (int k = 0; k < 16; ++k) acc[k] = 0ull;

                #pragma unroll
                for (int s = 0; s < 2; ++s) {
                    const int xoff = q * 8 + bq;
                    ulonglong2 xi[4], xj[4];
                    #pragma unroll
                    for (int r = 0; r < 4; ++r) {
                        xi[r] = sm4[((i0 + r) * 2 + s) * 32 + xoff];
                        xj[r] = sm4[((j0 + r) * 2 + s) * 32 + xoff];
                    }
                    const int we = ph * 8 + 2 * q + s;   // global e4 index
                    #pragma unroll
                    for (int a = 0; a < 4; ++a) {
                        #pragma unroll
                        for (int bb = 0; bb < 4; ++bb) {
                            ulonglong2 wv = __ldg(&w4[(size_t)(pb[a] + bb) * 16 + we]);
                            const int k = a * 4 + bb;
                            acc[k] = fma2(mul2(xi[a].x, xj[bb].x), wv.x, acc[k]);
                            acc[k] = fma2(mul2(xi[a].y, xj[bb].y), wv.y, acc[k]);
                        }
                    }
                }

                #pragma unroll
                for (int a = 0; a < 4; ++a)
                    #pragma unroll
                    for (int bb = 0; bb < 4; ++bb) {
                        float r = sum2(acc[a * 4 + bb]);
                        r += __shfl_xor_sync(0xffffffffu, r, 2);
                        r += __shfl_xor_sync(0xffffffffu, r, 1);
                        if (q == 0) {
                            float* po = orow + pb[a] + bb;
                            if (ph) r += *po;
                            *po = r;
                        }
                    }
            } else {
                // diagonal tile: group g, 6 intra-group pairs
                const int g  = t - NFULL;
                const int i0 = 4 * g;
                const int pa[6] = {0, 0, 0, 1, 1, 2};
                const int pc[6] = {1, 2, 3, 2, 3, 3};
                int pidx[6];
                #pragma unroll
                for (int k = 0; k < 6; ++k)
                    pidx[k] = pair_off(i0 + pa[k]) + (pc[k] - pa[k] - 1);

                unsigned long long acc[6];
                #pragma unroll
                for (int k = 0; k < 6; ++k) acc[k] = 0ull;

                #pragma unroll
                for (int s = 0; s < 2; ++s) {
                    const int xoff = q * 8 + bq;
                    ulonglong2 x[4];
                    #pragma unroll
                    for (int r = 0; r < 4; ++r)
                        x[r] = sm4[((i0 + r) * 2 + s) * 32 + xoff];
                    const int we = ph * 8 + 2 * q + s;
                    #pragma unroll
                    for (int k = 0; k < 6; ++k) {
                        ulonglong2 wv = __ldg(&w4[(size_t)pidx[k] * 16 + we]);
                        acc[k] = fma2(mul2(x[pa[k]].x, x[pc[k]].x), wv.x, acc[k]);
                        acc[k] = fma2(mul2(x[pa[k]].y, x[pc[k]].y), wv.y, acc[k]);
                    }
                }

                #pragma unroll
                for (int k = 0; k < 6; ++k) {
                    float r = sum2(acc[k]);
                    r += __shfl_xor_sync(0xffffffffu, r, 2);
                    r += __shfl_xor_sync(0xffffffffu, r, 1);
                    if (q == 0) {
                        float* po = orow + pidx[k];
                        if (ph) r += *po;
                        *po = r;
                    }
                }
            }
        }
    }
}

// ---------------------------------------------------------------------------
// Launch
// ---------------------------------------------------------------------------
extern "C" void kernel_launch(void* const* d_in, const int* in_sizes, int n_in,
                              void* d_out, int out_size)
{
    const float* inputs = (const float*)d_in[0];
    const float* kern   = (const float*)d_in[1];
    (void)n_in; (void)out_size;

    const int B = in_sizes[0] / (FDIM * EDIM);            // 2048
    const size_t smem_bytes = 2560 * sizeof(ulonglong2);  // 40 KB

    cudaFuncSetAttribute(interact_kernel,
                         cudaFuncAttributeMaxDynamicSharedMemorySize,
                         (int)smem_bytes);

    {
        const int n4 = NPAIR * EDIM / 4;
        ksum_kernel<<<(n4 + 255) / 256, 256>>>(kern);
    }
    interact_kernel<<<(B / BT) * 2, 256, smem_bytes>>>(inputs, (float*)d_out);
}

// round 9
// speedup vs baseline: 3.5918x; 3.5918x over previous
#include <cuda_runtime.h>

// Problem constants: B=2048, F=40, E=64, I=780
#define FDIM   40
#define EDIM   64
#define NPAIR  780
#define NGR    10            // field groups of 4
#define NFULL  45            // C(10,2) full 4x4 tiles
#define NTILE  55            // + 10 diagonal (intra-group) tiles
#define BT     8             // batches per block; lane = 4*b + e_quarter
#define STEPS  4             // float4 e-chunks per lane (16 e per lane)

// w scratch, step-major within each pair row:
//   g_ksum[p*64 + ((e4&3)*4 + (e4>>2))*4 + c]  holds ksum[p][4*e4+c]
__device__ float g_ksum[NPAIR * EDIM];

// ---------------------------------------------------------------------------
// Kernel 1: ksum[p][e] = sum_k kernel[k][p][e], written step-major.
// ---------------------------------------------------------------------------
__global__ void ksum_kernel(const float* __restrict__ kern)
{
    const int n4 = NPAIR * EDIM / 4;          // 12480 float4 chunks
    int idx4 = blockIdx.x * blockDim.x + threadIdx.x;
    if (idx4 >= n4) return;
    const float4* k4 = reinterpret_cast<const float4*>(kern);
    float4 s = make_float4(0.f, 0.f, 0.f, 0.f);
    #pragma unroll 8
    for (int k = 0; k < EDIM; ++k) {
        float4 v = k4[(size_t)k * n4 + idx4];
        s.x += v.x; s.y += v.y; s.z += v.z; s.w += v.w;
    }
    int p  = idx4 >> 4;
    int e4 = idx4 & 15;
    int perm = (e4 & 3) * 4 + (e4 >> 2);      // step-major permutation
    reinterpret_cast<float4*>(g_ksum)[p * 16 + perm] = s;
}

// ---------------------------------------------------------------------------
// f32x2 packed-math helpers
// ---------------------------------------------------------------------------
__device__ __forceinline__ unsigned long long mul2(unsigned long long a,
                                                   unsigned long long b)
{
    unsigned long long r;
    asm("mul.rn.f32x2 %0, %1, %2;" : "=l"(r) : "l"(a), "l"(b));
    return r;
}
__device__ __forceinline__ unsigned long long fma2(unsigned long long a,
                                                   unsigned long long b,
                                                   unsigned long long c)
{
    unsigned long long r;
    asm("fma.rn.f32x2 %0, %1, %2, %3;" : "=l"(r) : "l"(a), "l"(b), "l"(c));
    return r;
}
__device__ __forceinline__ float sum2(unsigned long long a)
{
    float lo, hi;
    asm("mov.b64 {%0, %1}, %2;" : "=f"(lo), "=f"(hi) : "l"(a));
    return lo + hi;
}

__device__ __forceinline__ int pair_off(int i) { return i * 39 - (i * (i - 1)) / 2; }

// ---------------------------------------------------------------------------
// Kernel 2. smem: sm4[(f*4 + s)*32 + ((4b+q) ^ s)] = float4 of A[b0+b][f][e],
// e-chunk e4 = 4q+s. Lane l = 4b+q owns (batch b, e-quarter q).
// Inner-loop w load: contiguous 64B per (pair, step) -> 2-sector LDG.
// ---------------------------------------------------------------------------
__global__ void __launch_bounds__(256, 2) interact_kernel(
    const float* __restrict__ A,    // (B, 40, 64)
    float*       __restrict__ out)  // (B, 780)
{
    extern __shared__ ulonglong2 sm4[];   // 40*4*32 entries = 80 KB

    const int tid  = threadIdx.x;
    const int lane = tid & 31;
    const int warp = tid >> 5;
    const int b0   = blockIdx.x * BT;

    // ---- stage 8 batches x 40 fields x 64 e, once ----
    const float4* A4 = reinterpret_cast<const float4*>(A);
    #pragma unroll 5
    for (int it = 0; it < 20; ++it) {
        int v  = it * 256 + tid;
        int e4 = v & 15;
        int b  = (v >> 4) & 7;
        int f  = v >> 7;
        float4 val = A4[(size_t)(b0 + b) * (FDIM * 16) + f * 16 + e4];
        int s = e4 & 3, q = e4 >> 2;
        sm4[(f * 4 + s) * 32 + ((4 * b + q) ^ s)] =
            *reinterpret_cast<ulonglong2*>(&val);
    }
    __syncthreads();

    const ulonglong2* w4 = reinterpret_cast<const ulonglong2*>(g_ksum);
    const int q  = lane & 3;       // e-quarter
    const int bq = lane >> 2;      // batch within block
    float* orow = out + (size_t)(b0 + bq) * NPAIR;

    for (int t = warp; t < NTILE; t += 8) {
        if (t < NFULL) {
            // ---- full 4x4 tile between groups gi < gj ----
            int gi = 0, cum = 0;
            while (cum + (NGR - 1 - gi) <= t) { cum += NGR - 1 - gi; ++gi; }
            int gj = gi + 1 + (t - cum);
            const int i0 = 4 * gi, j0 = 4 * gj;

            int pb[4];
            #pragma unroll
            for (int a = 0; a < 4; ++a)
                pb[a] = pair_off(i0 + a) + (j0 - (i0 + a) - 1);

            unsigned long long acc[16];
            #pragma unroll
            for (int k = 0; k < 16; ++k) acc[k] = 0ull;

            #pragma unroll
            for (int s = 0; s < STEPS; ++s) {
                const int sl = lane ^ s;
                ulonglong2 xi[4], xj[4];
                #pragma unroll
                for (int r = 0; r < 4; ++r) {
                    xi[r] = sm4[((i0 + r) * 4 + s) * 32 + sl];
                    xj[r] = sm4[((j0 + r) * 4 + s) * 32 + sl];
                }
                // step-major w: chunk for (pair, s, q) at p*16 + s*4 + q
                #pragma unroll
                for (int a = 0; a < 4; ++a) {
                    #pragma unroll
                    for (int bb = 0; bb < 4; ++bb) {
                        ulonglong2 wv =
                            __ldg(&w4[(size_t)(pb[a] + bb) * 16 + s * 4 + q]);
                        const int k = a * 4 + bb;
                        acc[k] = fma2(mul2(xi[a].x, xj[bb].x), wv.x, acc[k]);
                        acc[k] = fma2(mul2(xi[a].y, xj[bb].y), wv.y, acc[k]);
                    }
                }
            }

            #pragma unroll
            for (int a = 0; a < 4; ++a)
                #pragma unroll
                for (int bb = 0; bb < 4; ++bb) {
                    float r = sum2(acc[a * 4 + bb]);
                    r += __shfl_xor_sync(0xffffffffu, r, 2);
                    r += __shfl_xor_sync(0xffffffffu, r, 1);
                    if (q == 0) orow[pb[a] + bb] = r;
                }
        } else {
            // ---- diagonal tile: group g, 6 intra-group pairs ----
            const int g  = t - NFULL;
            const int i0 = 4 * g;
            const int pa[6]  = {0, 0, 0, 1, 1, 2};
            const int pc[6]  = {1, 2, 3, 2, 3, 3};
            int pidx[6];
            #pragma unroll
            for (int k = 0; k < 6; ++k)
                pidx[k] = pair_off(i0 + pa[k]) + (pc[k] - pa[k] - 1);

            unsigned long long acc[6];
            #pragma unroll
            for (int k = 0; k < 6; ++k) acc[k] = 0ull;

            #pragma unroll
            for (int s = 0; s < STEPS; ++s) {
                const int sl = lane ^ s;
                ulonglong2 x[4];
                #pragma unroll
                for (int r = 0; r < 4; ++r)
                    x[r] = sm4[((i0 + r) * 4 + s) * 32 + sl];
                #pragma unroll
                for (int k = 0; k < 6; ++k) {
                    ulonglong2 wv =
                        __ldg(&w4[(size_t)pidx[k] * 16 + s * 4 + q]);
                    acc[k] = fma2(mul2(x[pa[k]].x, x[pc[k]].x), wv.x, acc[k]);
                    acc[k] = fma2(mul2(x[pa[k]].y, x[pc[k]].y), wv.y, acc[k]);
                }
            }

            #pragma unroll
            for (int k = 0; k < 6; ++k) {
                float r = sum2(acc[k]);
                r += __shfl_xor_sync(0xffffffffu, r, 2);
                r += __shfl_xor_sync(0xffffffffu, r, 1);
                if (q == 0) orow[pidx[k]] = r;
            }
        }
    }
}

// ---------------------------------------------------------------------------
// Launch
// ---------------------------------------------------------------------------
extern "C" void kernel_launch(void* const* d_in, const int* in_sizes, int n_in,
                              void* d_out, int out_size)
{
    const float* inputs = (const float*)d_in[0];
    const float* kern   = (const float*)d_in[1];
    (void)n_in; (void)out_size;

    const int B = in_sizes[0] / (FDIM * EDIM);              // 2048
    const size_t smem_bytes = (size_t)FDIM * 4 * 32 * 16;   // 81920 = 80 KB

    cudaFuncSetAttribute(interact_kernel,
                         cudaFuncAttributeMaxDynamicSharedMemorySize,
                         (int)smem_bytes);

    {
        const int n4 = NPAIR * EDIM / 4;
        ksum_kernel<<<(n4 + 255) / 256, 256>>>(kern);
    }
    interact_kernel<<<B / BT, 256, smem_bytes>>>(inputs, (float*)d_out);
}